// round 7
// baseline (speedup 1.0000x reference)
#include <cuda_runtime.h>
#include <cuda_bf16.h>
#include <cstdint>

// Problem constants
#define BATCH 32
#define DIM   256
#define HW    1024
#define NPTS  32768
#define KCODE 1024
#define ZQ_ELEMS 8388608
#define IDX_OFF  ZQ_ELEMS
#define LOSS_OFF (ZQ_ELEMS + NPTS)

#define NSLOT 3           // top-3 per (thread,row) slot
#define NCROW 24          // 8 slots * 3 candidates per row
#define MARGIN 7e-4f

// Scratch (device globals)
__device__ float          g_zt [NPTS * DIM];     // z^T fp32 [N,D]
__device__ __nv_bfloat16  g_zth[NPTS * DIM];     // z^T bf16
__device__ __nv_bfloat16  g_cbh[KCODE * DIM];    // codebook bf16
__device__ int            g_idx[NPTS];
__device__ float          g_normE[KCODE];        // t2
__device__ float          g_t1[NPTS];            // t1 (sequential emulation)
__device__ float          g_candV[NPTS * NCROW];
__device__ int            g_candI[NPTS * NCROW];
__device__ double         g_loss;
__device__ unsigned       g_done;                // zero-init; reset after use

// ================= generic PTX helpers =================
__device__ __forceinline__ uint32_t smem_u32(const void* p) {
    uint32_t a;
    asm("{ .reg .u64 t; cvta.to.shared.u64 t, %1; cvt.u32.u64 %0, t; }" : "=r"(a) : "l"(p));
    return a;
}
#define CP_ASYNC16(dst, src) \
    asm volatile("cp.async.cg.shared.global [%0], [%1], 16;" :: "r"(dst), "l"(src) : "memory")
#define CP_COMMIT() asm volatile("cp.async.commit_group;" ::: "memory")
#define CP_WAIT0()  asm volatile("cp.async.wait_group 0;" ::: "memory")
#define CP_WAIT1()  asm volatile("cp.async.wait_group 1;" ::: "memory")

#define LDSM4(r0, r1, r2, r3, addr) \
    asm volatile("ldmatrix.sync.aligned.m8n8.x4.shared.b16 {%0,%1,%2,%3}, [%4];" \
        : "=r"(r0), "=r"(r1), "=r"(r2), "=r"(r3) : "r"(addr))

#define MMA16816(C, A, b0, b1) \
    asm volatile("mma.sync.aligned.m16n8k16.row.col.f32.bf16.bf16.f32 " \
        "{%0,%1,%2,%3},{%4,%5,%6,%7},{%8,%9},{%0,%1,%2,%3};" \
        : "+f"((C)[0]), "+f"((C)[1]), "+f"((C)[2]), "+f"((C)[3]) \
        : "r"((A)[0]), "r"((A)[1]), "r"((A)[2]), "r"((A)[3]), "r"(b0), "r"(b1))

// swizzled smem offset for bf16 tile rows of 512B, 16B chunks
__device__ __forceinline__ uint32_t sw_off(int row, int c16) {
    return (uint32_t)(row * 512 + ((c16 ^ (row & 7)) << 4));
}

// ================= Kernel 1: codebook norms + bf16 cvt + loss reset =============
__global__ void norms_k(const float* __restrict__ cb) {
    int k = blockIdx.x;
    float x = cb[k * DIM + threadIdx.x];
    g_cbh[k * DIM + threadIdx.x] = __float2bfloat16(x);
    float v = __fmul_rn(x, x);
    __shared__ float s[8];
    #pragma unroll
    for (int o = 16; o; o >>= 1) v += __shfl_down_sync(0xffffffffu, v, o);
    if ((threadIdx.x & 31) == 0) s[threadIdx.x >> 5] = v;
    __syncthreads();
    if (threadIdx.x < 8) {
        float t = s[threadIdx.x];
        #pragma unroll
        for (int o = 4; o; o >>= 1) t += __shfl_down_sync(0xffu, t, o);
        if (threadIdx.x == 0) {
            g_normE[k] = t;
            if (blockIdx.x == 0) g_loss = 0.0;
        }
    }
}

// ================= Kernel 2: transpose z -> zt (f32 + bf16) =====================
__global__ void transpose_k(const float* __restrict__ z) {
    __shared__ float tile[32][33];
    int b  = blockIdx.z;
    int p0 = blockIdx.x * 32;
    int d0 = blockIdx.y * 32;
    const float* src = z + (size_t)b * DIM * HW;
    #pragma unroll
    for (int i = 0; i < 32; i += 8)
        tile[threadIdx.y + i][threadIdx.x] = src[(d0 + threadIdx.y + i) * HW + p0 + threadIdx.x];
    __syncthreads();
    #pragma unroll
    for (int i = 0; i < 32; i += 8) {
        float v = tile[threadIdx.x][threadIdx.y + i];
        int o = (b * HW + p0 + threadIdx.y + i) * DIM + d0 + threadIdx.x;
        g_zt[o]  = v;
        g_zth[o] = __float2bfloat16(v);
    }
}

// ================= Kernel 2b: t1 from original z layout (coalesced, seq order) ==
__global__ __launch_bounds__(256) void rownorm_z_k(const float* __restrict__ z) {
    int b = blockIdx.x >> 2;
    int p = ((blockIdx.x & 3) << 8) + threadIdx.x;
    const float* src = z + (size_t)b * DIM * HW + p;
    float acc = 0.0f;
    #pragma unroll 8
    for (int d = 0; d < 256; d++) {
        float x = src[(size_t)d * HW];
        acc = __fadd_rn(acc, __fmul_rn(x, x));   // strict d=0..255 sequential chain
    }
    g_t1[(b << 10) + p] = acc;
}

// ================= Kernel 3: HMMA bf16 GEMM, 3 CTAs/SM, 64-row x 32-code tiles ==
// smem: A 32KB | B0 16KB | B1 16KB | NE 4KB  = 68KB -> 3 CTAs/SM
#define AS_OFF 0
#define BS_OFF 32768
#define NE_OFF 65536
#define HM_SMEM 69632

__global__ __launch_bounds__(128, 3) void gemm_hmma_k() {
    extern __shared__ char smem[];
    const uint32_t sb = smem_u32(smem);
    const int tid  = threadIdx.x;
    const int lane = tid & 31;
    const int wid  = tid >> 5;       // 4 warps
    const int wm   = wid & 1;        // 2 warps over M (32 rows each)
    const int wn   = wid >> 1;       // 2 warps over N (16 codes each)
    const int m0   = blockIdx.x * 64;

    // ---- prologue group 0: A (64 rows x 256) + B chunk 0 (32 codes) + normE ----
    #pragma unroll 4
    for (int i = tid; i < 2048; i += 128) {
        int row = i >> 5, c16 = i & 31;
        const __nv_bfloat16* src = &g_zth[(size_t)(m0 + row) * DIM + c16 * 8];
        CP_ASYNC16(sb + AS_OFF + sw_off(row, c16), (const void*)src);
    }
    #pragma unroll 4
    for (int i = tid; i < 1024; i += 128) {
        int row = i >> 5, c16 = i & 31;
        const __nv_bfloat16* src = &g_cbh[(size_t)row * DIM + c16 * 8];
        CP_ASYNC16(sb + BS_OFF + sw_off(row, c16), (const void*)src);
    }
    #pragma unroll
    for (int i = tid; i < 256; i += 128)
        CP_ASYNC16(sb + NE_OFF + i * 16, (const void*)&g_normE[i * 4]);
    CP_COMMIT();
    // ---- prologue group 1: B chunk 1 ----
    #pragma unroll 4
    for (int i = tid; i < 1024; i += 128) {
        int row = i >> 5, c16 = i & 31;
        const __nv_bfloat16* src = &g_cbh[(size_t)(32 + row) * DIM + c16 * 8];
        CP_ASYNC16(sb + BS_OFF + 16384 + sw_off(row, c16), (const void*)src);
    }
    CP_COMMIT();

    // top-3 per slot: s = mt*2 + h (4 row-slots per thread)
    float tv[4][NSLOT];
    int   ts[4][NSLOT];
    #pragma unroll
    for (int s = 0; s < 4; s++)
        #pragma unroll
        for (int j = 0; j < NSLOT; j++) { tv[s][j] = 3.4e38f; ts[s][j] = 0; }

    const float2* nep = (const float2*)(smem + NE_OFF);

    for (int c = 0; c < 32; ++c) {
        if (c < 31) CP_WAIT1(); else CP_WAIT0();
        __syncthreads();

        const uint32_t Bbase = sb + BS_OFF + ((c & 1) << 14);
        float C[2][2][4];
        #pragma unroll
        for (int mt = 0; mt < 2; mt++)
            #pragma unroll
            for (int nt = 0; nt < 2; nt++)
                #pragma unroll
                for (int q = 0; q < 4; q++) C[mt][nt][q] = 0.0f;

        #pragma unroll
        for (int st = 0; st < 16; ++st) {
            uint32_t a[2][4];
            #pragma unroll
            for (int mt = 0; mt < 2; mt++) {
                int row = wm * 32 + mt * 16 + (lane & 15);
                int c16 = st * 2 + (lane >> 4);
                LDSM4(a[mt][0], a[mt][1], a[mt][2], a[mt][3], sb + AS_OFF + sw_off(row, c16));
            }
            uint32_t b[4];
            {
                int row = wn * 16 + ((lane >> 4) & 1) * 8 + (lane & 7);
                int c16 = st * 2 + ((lane >> 3) & 1);
                LDSM4(b[0], b[1], b[2], b[3], Bbase + sw_off(row, c16));
            }
            #pragma unroll
            for (int mt = 0; mt < 2; mt++) {
                MMA16816(C[mt][0], a[mt], b[0], b[1]);
                MMA16816(C[mt][1], a[mt], b[2], b[3]);
            }
        }
        __syncthreads();   // all warps done reading buf[c&1]

        // prefetch chunk c+2 into buf[c&1] (async; overlaps epilogue)
        if (c + 2 < 32) {
            #pragma unroll 4
            for (int i = tid; i < 1024; i += 128) {
                int row = i >> 5, c16 = i & 31;
                const __nv_bfloat16* src = &g_cbh[(size_t)((c + 2) * 32 + row) * DIM + c16 * 8];
                CP_ASYNC16(Bbase + sw_off(row, c16), (const void*)src);
            }
            CP_COMMIT();
        }

        // epilogue: dist = ne - 2*dot (ne from smem), top-3 per row-slot
        #pragma unroll
        for (int mt = 0; mt < 2; mt++) {
            #pragma unroll
            for (int nt = 0; nt < 2; nt++) {
                int col = c * 32 + wn * 16 + nt * 8 + ((lane & 3) << 1);
                float2 ne = nep[col >> 1];
                float dv[4];
                dv[0] = __fmaf_rn(-2.0f, C[mt][nt][0], ne.x);
                dv[1] = __fmaf_rn(-2.0f, C[mt][nt][1], ne.y);
                dv[2] = __fmaf_rn(-2.0f, C[mt][nt][2], ne.x);
                dv[3] = __fmaf_rn(-2.0f, C[mt][nt][3], ne.y);
                #pragma unroll
                for (int q = 0; q < 4; q++) {
                    const int s = mt * 2 + (q >> 1);
                    const int idx = col + (q & 1);
                    const float v = dv[q];
                    if (v < tv[s][2]) {
                        if (v < tv[s][1]) {
                            tv[s][2] = tv[s][1]; ts[s][2] = ts[s][1];
                            if (v < tv[s][0]) {
                                tv[s][1] = tv[s][0]; ts[s][1] = ts[s][0];
                                tv[s][0] = v;        ts[s][0] = idx;
                            } else { tv[s][1] = v; ts[s][1] = idx; }
                        } else { tv[s][2] = v; ts[s][2] = idx; }
                    }
                }
            }
        }
    }

    // write candidates: row owned by 8 threads (2 n-warps x 4 lane%4), 3 each
    #pragma unroll
    for (int mt = 0; mt < 2; mt++) {
        #pragma unroll
        for (int h = 0; h < 2; h++) {
            int row  = m0 + wm * 32 + mt * 16 + h * 8 + (lane >> 2);
            int slot = wn * 4 + (lane & 3);
            int s = mt * 2 + h;
            #pragma unroll
            for (int j = 0; j < NSLOT; j++) {
                g_candV[(size_t)row * NCROW + slot * NSLOT + j] = tv[s][j];
                g_candI[(size_t)row * NCROW + slot * NSLOT + j] = ts[s][j];
            }
        }
    }
}

// ================= Kernel 3b: warp-per-row exact rescore + idx output ===========
__global__ __launch_bounds__(256) void rescore_k(const float* __restrict__ cb,
                                                 float* __restrict__ out, int write_idx) {
    const int wid  = threadIdx.x >> 5;
    const int lane = threadIdx.x & 31;
    const int row  = blockIdx.x * 8 + wid;
    const float* cv = &g_candV[(size_t)row * NCROW];
    const int*   ci = &g_candI[(size_t)row * NCROW];

    float v1 = (lane < NCROW) ? cv[lane] : 3.4e38f;
    int   i1 = (lane < NCROW) ? ci[lane] : 0;

    float vmin = v1;
    #pragma unroll
    for (int o = 16; o; o >>= 1) vmin = fminf(vmin, __shfl_xor_sync(0xffffffffu, vmin, o));
    const float thr = vmin + MARGIN;

    unsigned m1 = __ballot_sync(0xffffffffu, v1 <= thr);

    int bestI;
    if (__popc(m1) == 1) {
        // unique candidate within margin: bf16 error << MARGIN => exact argmin.
        bestI = __shfl_sync(0xffffffffu, i1, __ffs(m1) - 1);
    } else {
        const float4* zp = (const float4*)&g_zt[(size_t)row * DIM + lane * 8];
        const float4 za = zp[0], zb = zp[1];
        const float t1 = g_t1[row];
        float bestD = 3.4e38f;
        bestI = 0x7fffffff;
        while (m1) {
            int l = __ffs(m1) - 1; m1 &= m1 - 1;
            int idx = __shfl_sync(0xffffffffu, i1, l);
            const float4* cp = (const float4*)&cb[(size_t)idx * DIM + lane * 8];
            float4 ca = cp[0], cb4 = cp[1];
            float p = 0.0f;
            p = __fmaf_rn(za.x, ca.x, p);  p = __fmaf_rn(za.y, ca.y, p);
            p = __fmaf_rn(za.z, ca.z, p);  p = __fmaf_rn(za.w, ca.w, p);
            p = __fmaf_rn(zb.x, cb4.x, p); p = __fmaf_rn(zb.y, cb4.y, p);
            p = __fmaf_rn(zb.z, cb4.z, p); p = __fmaf_rn(zb.w, cb4.w, p);
            #pragma unroll
            for (int o = 16; o; o >>= 1) p += __shfl_xor_sync(0xffffffffu, p, o);
            float dd = __fsub_rn(__fadd_rn(t1, __ldg(&g_normE[idx])), __fmul_rn(2.0f, p));
            if (dd < bestD || (dd == bestD && idx < bestI)) { bestD = dd; bestI = idx; }
        }
        bestI = __shfl_sync(0xffffffffu, bestI, 0);
    }
    if (lane == 0) {
        g_idx[row] = bestI;
        if (write_idx) out[IDX_OFF + row] = (float)bestI;
    }
}

// ================= Kernel 4: straight-through z_q + loss + last-block finalize ==
#define GL_BLOCKS 4096
__global__ __launch_bounds__(256) void gather_loss_k(const float* __restrict__ z,
                                                     const float* __restrict__ cb,
                                                     float* __restrict__ out,
                                                     int write_loss) {
    float local = 0.0f;
    for (int i = blockIdx.x * 256 + threadIdx.x; i < ZQ_ELEMS; i += GL_BLOCKS * 256) {
        int p = i & (HW - 1);
        int d = (i >> 10) & (DIM - 1);
        int b = i >> 18;
        int n = (b << 10) | p;
        float zv = z[i];
        float q  = cb[g_idx[n] * DIM + d];
        float diff = __fsub_rn(q, zv);
        out[i] = __fadd_rn(zv, diff);
        local = __fmaf_rn(diff, diff, local);
    }
    __shared__ float s[8];
    #pragma unroll
    for (int o = 16; o; o >>= 1) local += __shfl_down_sync(0xffffffffu, local, o);
    if ((threadIdx.x & 31) == 0) s[threadIdx.x >> 5] = local;
    __syncthreads();
    if (threadIdx.x < 8) {
        float t = s[threadIdx.x];
        #pragma unroll
        for (int o = 4; o; o >>= 1) t += __shfl_down_sync(0xffu, t, o);
        if (threadIdx.x == 0) {
            atomicAdd(&g_loss, (double)t);
            __threadfence();
            unsigned r = atomicAdd(&g_done, 1u);
            if (r == GL_BLOCKS - 1) {                 // last block: finalize
                double total = atomicAdd(&g_loss, 0.0);
                if (write_loss) out[LOSS_OFF] = (float)(1.25 * total / (double)ZQ_ELEMS);
                g_done = 0;                            // reset for next graph replay
            }
        }
    }
}

extern "C" void kernel_launch(void* const* d_in, const int* in_sizes, int n_in,
                              void* d_out, int out_size) {
    const float* z  = (const float*)d_in[0];
    const float* cb = (const float*)d_in[1];
    float* out = (float*)d_out;

    cudaFuncSetAttribute(gemm_hmma_k, cudaFuncAttributeMaxDynamicSharedMemorySize, HM_SMEM);

    int write_idx  = (out_size >= IDX_OFF + NPTS);
    int write_loss = (out_size >= LOSS_OFF + 1);

    norms_k<<<KCODE, 256>>>(cb);
    transpose_k<<<dim3(HW / 32, DIM / 32, BATCH), dim3(32, 8)>>>(z);
    rownorm_z_k<<<BATCH * 4, 256>>>(z);
    gemm_hmma_k<<<NPTS / 64, 128, HM_SMEM>>>();
    rescore_k<<<NPTS / 8, 256>>>(cb, out, write_idx);
    gather_loss_k<<<GL_BLOCKS, 256>>>(z, cb, out, write_loss);
}

// round 8
// speedup vs baseline: 1.2393x; 1.2393x over previous
#include <cuda_runtime.h>
#include <cuda_bf16.h>
#include <cstdint>

// Problem constants
#define BATCH 32
#define DIM   256
#define HW    1024
#define NPTS  32768
#define KCODE 1024
#define ZQ_ELEMS 8388608
#define IDX_OFF  ZQ_ELEMS
#define LOSS_OFF (ZQ_ELEMS + NPTS)

#define NSLOT 3           // top-3 per (thread,row) slot
#define NCROW 24          // 8 slots * 3 candidates per row
#define MARGIN 7e-4f

// Scratch (device globals)
__device__ float          g_zt [NPTS * DIM];     // z^T fp32 [N,D]
__device__ __nv_bfloat16  g_zth[NPTS * DIM];     // z^T bf16
__device__ __nv_bfloat16  g_cbh[KCODE * DIM];    // codebook bf16
__device__ int            g_idx[NPTS];
__device__ float          g_normE[KCODE];        // t2
__device__ float          g_t1[NPTS];            // t1 (sequential emulation)
__device__ float          g_candV[NPTS * NCROW];
__device__ int            g_candI[NPTS * NCROW];
__device__ double         g_loss;
__device__ unsigned       g_done;                // zero-init; reset after use

// ================= generic PTX helpers =================
__device__ __forceinline__ uint32_t smem_u32(const void* p) {
    uint32_t a;
    asm("{ .reg .u64 t; cvta.to.shared.u64 t, %1; cvt.u32.u64 %0, t; }" : "=r"(a) : "l"(p));
    return a;
}
#define CP_ASYNC16(dst, src) \
    asm volatile("cp.async.cg.shared.global [%0], [%1], 16;" :: "r"(dst), "l"(src) : "memory")
#define CP_COMMIT() asm volatile("cp.async.commit_group;" ::: "memory")
#define CP_WAIT0()  asm volatile("cp.async.wait_group 0;" ::: "memory")
#define CP_WAIT1()  asm volatile("cp.async.wait_group 1;" ::: "memory")

#define LDSM4(r0, r1, r2, r3, addr) \
    asm volatile("ldmatrix.sync.aligned.m8n8.x4.shared.b16 {%0,%1,%2,%3}, [%4];" \
        : "=r"(r0), "=r"(r1), "=r"(r2), "=r"(r3) : "r"(addr))

#define MMA16816(C, A, b0, b1) \
    asm volatile("mma.sync.aligned.m16n8k16.row.col.f32.bf16.bf16.f32 " \
        "{%0,%1,%2,%3},{%4,%5,%6,%7},{%8,%9},{%0,%1,%2,%3};" \
        : "+f"((C)[0]), "+f"((C)[1]), "+f"((C)[2]), "+f"((C)[3]) \
        : "r"((A)[0]), "r"((A)[1]), "r"((A)[2]), "r"((A)[3]), "r"(b0), "r"(b1))

// swizzled smem offset for bf16 tile rows of 512B, 16B chunks
__device__ __forceinline__ uint32_t sw_off(int row, int c16) {
    return (uint32_t)(row * 512 + ((c16 ^ (row & 7)) << 4));
}

// ================= Kernel 1: codebook norms + bf16 cvt + loss reset =============
__global__ void norms_k(const float* __restrict__ cb) {
    int k = blockIdx.x;
    float x = cb[k * DIM + threadIdx.x];
    g_cbh[k * DIM + threadIdx.x] = __float2bfloat16(x);
    float v = __fmul_rn(x, x);
    __shared__ float s[8];
    #pragma unroll
    for (int o = 16; o; o >>= 1) v += __shfl_down_sync(0xffffffffu, v, o);
    if ((threadIdx.x & 31) == 0) s[threadIdx.x >> 5] = v;
    __syncthreads();
    if (threadIdx.x < 8) {
        float t = s[threadIdx.x];
        #pragma unroll
        for (int o = 4; o; o >>= 1) t += __shfl_down_sync(0xffu, t, o);
        if (threadIdx.x == 0) {
            g_normE[k] = t;
            if (blockIdx.x == 0) g_loss = 0.0;
        }
    }
}

// ================= Kernel 2: transpose z -> zt (f32 + bf16) =====================
__global__ void transpose_k(const float* __restrict__ z) {
    __shared__ float tile[32][33];
    int b  = blockIdx.z;
    int p0 = blockIdx.x * 32;
    int d0 = blockIdx.y * 32;
    const float* src = z + (size_t)b * DIM * HW;
    #pragma unroll
    for (int i = 0; i < 32; i += 8)
        tile[threadIdx.y + i][threadIdx.x] = src[(d0 + threadIdx.y + i) * HW + p0 + threadIdx.x];
    __syncthreads();
    #pragma unroll
    for (int i = 0; i < 32; i += 8) {
        float v = tile[threadIdx.x][threadIdx.y + i];
        int o = (b * HW + p0 + threadIdx.y + i) * DIM + d0 + threadIdx.x;
        g_zt[o]  = v;
        g_zth[o] = __float2bfloat16(v);
    }
}

// ================= Kernel 2b: t1 from original z layout (coalesced, seq order) ==
__global__ __launch_bounds__(256) void rownorm_z_k(const float* __restrict__ z) {
    int b = blockIdx.x >> 2;
    int p = ((blockIdx.x & 3) << 8) + threadIdx.x;
    const float* src = z + (size_t)b * DIM * HW + p;
    float acc = 0.0f;
    #pragma unroll 8
    for (int d = 0; d < 256; d++) {
        float x = src[(size_t)d * HW];
        acc = __fadd_rn(acc, __fmul_rn(x, x));   // strict d=0..255 sequential chain
    }
    g_t1[(b << 10) + p] = acc;
}

// ================= Kernel 3: HMMA bf16 GEMM (R6 shape + frag pipelining) ========
// smem: A 32KB | B0 32KB | B1 32KB | NE 4KB = 100KB -> 2 CTAs/SM
#define AS_OFF 0
#define BS_OFF 32768
#define NE_OFF 98304
#define HM_SMEM 102400

__global__ __launch_bounds__(128, 2) void gemm_hmma_k() {
    extern __shared__ char smem[];
    const uint32_t sb = smem_u32(smem);
    const int tid  = threadIdx.x;
    const int lane = tid & 31;
    const int wid  = tid >> 5;       // 4 warps
    const int wm   = wid & 1;        // 2 warps over M (32 rows each)
    const int wn   = wid >> 1;       // 2 warps over N (32 codes each)
    const int m0   = blockIdx.x * 64;

    // ---- prologue: A (64 rows) + B chunk 0 + normE (group 0), B chunk 1 (group 1)
    #pragma unroll 4
    for (int i = tid; i < 2048; i += 128) {
        int row = i >> 5, c16 = i & 31;
        const __nv_bfloat16* src = &g_zth[(size_t)(m0 + row) * DIM + c16 * 8];
        CP_ASYNC16(sb + AS_OFF + sw_off(row, c16), (const void*)src);
    }
    #pragma unroll 4
    for (int i = tid; i < 2048; i += 128) {
        int row = i >> 5, c16 = i & 31;
        const __nv_bfloat16* src = &g_cbh[(size_t)row * DIM + c16 * 8];
        CP_ASYNC16(sb + BS_OFF + sw_off(row, c16), (const void*)src);
    }
    #pragma unroll
    for (int i = tid; i < 256; i += 128)
        CP_ASYNC16(sb + NE_OFF + i * 16, (const void*)&g_normE[i * 4]);
    CP_COMMIT();
    #pragma unroll 4
    for (int i = tid; i < 2048; i += 128) {
        int row = i >> 5, c16 = i & 31;
        const __nv_bfloat16* src = &g_cbh[(size_t)(64 + row) * DIM + c16 * 8];
        CP_ASYNC16(sb + BS_OFF + 32768 + sw_off(row, c16), (const void*)src);
    }
    CP_COMMIT();

    // top-3 per slot: s = mt*2 + h (4 row-slots per thread)
    float tv[4][NSLOT];
    int   ts[4][NSLOT];
    #pragma unroll
    for (int s = 0; s < 4; s++)
        #pragma unroll
        for (int j = 0; j < NSLOT; j++) { tv[s][j] = 3.4e38f; ts[s][j] = 0; }

    const float2* nep = (const float2*)(smem + NE_OFF);

    // fragment addresses (depend only on lane, st)
    const int arow = wm * 32 + (lane & 15);       // +mt*16
    const int acol_sel = (lane >> 4);             // +st*2
    const int brow0 = wn * 32 + ((lane >> 4) & 1) * 8 + (lane & 7);   // +p*16
    const int bcol_sel = ((lane >> 3) & 1);       // +st*2

    for (int c = 0; c < 16; ++c) {
        if (c < 15) CP_WAIT1(); else CP_WAIT0();
        __syncthreads();

        const uint32_t Bbase = sb + BS_OFF + ((c & 1) << 15);
        float C[2][4][4];
        #pragma unroll
        for (int mt = 0; mt < 2; mt++)
            #pragma unroll
            for (int nt = 0; nt < 4; nt++)
                #pragma unroll
                for (int q = 0; q < 4; q++) C[mt][nt][q] = 0.0f;

        // fragment double buffers
        uint32_t a[2][2][4], b[2][2][4];

        // preload st=0
        {
            int c16 = acol_sel;
            LDSM4(a[0][0][0], a[0][0][1], a[0][0][2], a[0][0][3], sb + AS_OFF + sw_off(arow,      c16));
            LDSM4(a[0][1][0], a[0][1][1], a[0][1][2], a[0][1][3], sb + AS_OFF + sw_off(arow + 16, c16));
            int bc = bcol_sel;
            LDSM4(b[0][0][0], b[0][0][1], b[0][0][2], b[0][0][3], Bbase + sw_off(brow0,      bc));
            LDSM4(b[0][1][0], b[0][1][1], b[0][1][2], b[0][1][3], Bbase + sw_off(brow0 + 16, bc));
        }

        #pragma unroll
        for (int st = 0; st < 16; ++st) {
            const int cur = st & 1, nxt = cur ^ 1;
            if (st < 15) {   // prefetch next k-step fragments
                int c16 = (st + 1) * 2 + acol_sel;
                LDSM4(a[nxt][0][0], a[nxt][0][1], a[nxt][0][2], a[nxt][0][3], sb + AS_OFF + sw_off(arow,      c16));
                LDSM4(a[nxt][1][0], a[nxt][1][1], a[nxt][1][2], a[nxt][1][3], sb + AS_OFF + sw_off(arow + 16, c16));
                int bc = (st + 1) * 2 + bcol_sel;
                LDSM4(b[nxt][0][0], b[nxt][0][1], b[nxt][0][2], b[nxt][0][3], Bbase + sw_off(brow0,      bc));
                LDSM4(b[nxt][1][0], b[nxt][1][1], b[nxt][1][2], b[nxt][1][3], Bbase + sw_off(brow0 + 16, bc));
            }
            #pragma unroll
            for (int mt = 0; mt < 2; mt++)
                #pragma unroll
                for (int nt = 0; nt < 4; nt++)
                    MMA16816(C[mt][nt], a[cur][mt], b[cur][nt >> 1][(nt & 1) * 2], b[cur][nt >> 1][(nt & 1) * 2 + 1]);
        }
        __syncthreads();   // all warps done reading buf[c&1]

        // prefetch chunk c+2 into buf[c&1] (async; overlaps epilogue)
        if (c + 2 < 16) {
            #pragma unroll 4
            for (int i = tid; i < 2048; i += 128) {
                int row = i >> 5, c16 = i & 31;
                const __nv_bfloat16* src = &g_cbh[(size_t)((c + 2) * 64 + row) * DIM + c16 * 8];
                CP_ASYNC16(Bbase + sw_off(row, c16), (const void*)src);
            }
            CP_COMMIT();
        }

        // epilogue: dist = ne - 2*dot (ne from smem), top-3 per row-slot
        #pragma unroll
        for (int mt = 0; mt < 2; mt++) {
            #pragma unroll
            for (int nt = 0; nt < 4; nt++) {
                int col = c * 64 + wn * 32 + nt * 8 + ((lane & 3) << 1);
                float2 ne = nep[col >> 1];
                float dv[4];
                dv[0] = __fmaf_rn(-2.0f, C[mt][nt][0], ne.x);
                dv[1] = __fmaf_rn(-2.0f, C[mt][nt][1], ne.y);
                dv[2] = __fmaf_rn(-2.0f, C[mt][nt][2], ne.x);
                dv[3] = __fmaf_rn(-2.0f, C[mt][nt][3], ne.y);
                #pragma unroll
                for (int q = 0; q < 4; q++) {
                    const int s = mt * 2 + (q >> 1);
                    const int idx = col + (q & 1);
                    const float v = dv[q];
                    if (v < tv[s][2]) {
                        if (v < tv[s][1]) {
                            tv[s][2] = tv[s][1]; ts[s][2] = ts[s][1];
                            if (v < tv[s][0]) {
                                tv[s][1] = tv[s][0]; ts[s][1] = ts[s][0];
                                tv[s][0] = v;        ts[s][0] = idx;
                            } else { tv[s][1] = v; ts[s][1] = idx; }
                        } else { tv[s][2] = v; ts[s][2] = idx; }
                    }
                }
            }
        }
    }

    // write candidates: row owned by 8 threads (2 n-warps x 4 lane%4), 3 each
    #pragma unroll
    for (int mt = 0; mt < 2; mt++) {
        #pragma unroll
        for (int h = 0; h < 2; h++) {
            int row  = m0 + wm * 32 + mt * 16 + h * 8 + (lane >> 2);
            int slot = wn * 4 + (lane & 3);
            int s = mt * 2 + h;
            #pragma unroll
            for (int j = 0; j < NSLOT; j++) {
                g_candV[(size_t)row * NCROW + slot * NSLOT + j] = tv[s][j];
                g_candI[(size_t)row * NCROW + slot * NSLOT + j] = ts[s][j];
            }
        }
    }
}

// ================= Kernel 3b: warp-per-row exact rescore + idx output ===========
__global__ __launch_bounds__(256) void rescore_k(const float* __restrict__ cb,
                                                 float* __restrict__ out, int write_idx) {
    const int wid  = threadIdx.x >> 5;
    const int lane = threadIdx.x & 31;
    const int row  = blockIdx.x * 8 + wid;
    const float* cv = &g_candV[(size_t)row * NCROW];
    const int*   ci = &g_candI[(size_t)row * NCROW];

    float v1 = (lane < NCROW) ? cv[lane] : 3.4e38f;
    int   i1 = (lane < NCROW) ? ci[lane] : 0;

    float vmin = v1;
    #pragma unroll
    for (int o = 16; o; o >>= 1) vmin = fminf(vmin, __shfl_xor_sync(0xffffffffu, vmin, o));
    const float thr = vmin + MARGIN;

    unsigned m1 = __ballot_sync(0xffffffffu, v1 <= thr);

    int bestI;
    if (__popc(m1) == 1) {
        // unique candidate within margin: bf16 error << MARGIN => exact argmin.
        bestI = __shfl_sync(0xffffffffu, i1, __ffs(m1) - 1);
    } else {
        const float4* zp = (const float4*)&g_zt[(size_t)row * DIM + lane * 8];
        const float4 za = zp[0], zb = zp[1];
        const float t1 = g_t1[row];
        float bestD = 3.4e38f;
        bestI = 0x7fffffff;
        while (m1) {
            int l = __ffs(m1) - 1; m1 &= m1 - 1;
            int idx = __shfl_sync(0xffffffffu, i1, l);
            const float4* cp = (const float4*)&cb[(size_t)idx * DIM + lane * 8];
            float4 ca = cp[0], cb4 = cp[1];
            float p = 0.0f;
            p = __fmaf_rn(za.x, ca.x, p);  p = __fmaf_rn(za.y, ca.y, p);
            p = __fmaf_rn(za.z, ca.z, p);  p = __fmaf_rn(za.w, ca.w, p);
            p = __fmaf_rn(zb.x, cb4.x, p); p = __fmaf_rn(zb.y, cb4.y, p);
            p = __fmaf_rn(zb.z, cb4.z, p); p = __fmaf_rn(zb.w, cb4.w, p);
            #pragma unroll
            for (int o = 16; o; o >>= 1) p += __shfl_xor_sync(0xffffffffu, p, o);
            float dd = __fsub_rn(__fadd_rn(t1, __ldg(&g_normE[idx])), __fmul_rn(2.0f, p));
            if (dd < bestD || (dd == bestD && idx < bestI)) { bestD = dd; bestI = idx; }
        }
        bestI = __shfl_sync(0xffffffffu, bestI, 0);
    }
    if (lane == 0) {
        g_idx[row] = bestI;
        if (write_idx) out[IDX_OFF + row] = (float)bestI;
    }
}

// ================= Kernel 4: z_q + loss, float4 vectorized =======================
#define GL_BLOCKS 2048
__global__ __launch_bounds__(256) void gather_loss_k(const float* __restrict__ z,
                                                     const float* __restrict__ cb,
                                                     float* __restrict__ out,
                                                     int write_loss) {
    float local = 0.0f;
    const int nvec = ZQ_ELEMS / 4;
    for (int i4 = blockIdx.x * 256 + threadIdx.x; i4 < nvec; i4 += GL_BLOCKS * 256) {
        int i = i4 * 4;                       // 4 consecutive elems: same b, d
        int p = i & (HW - 1);
        int d = (i >> 10) & (DIM - 1);
        int b = i >> 18;
        int n = (b << 10) | p;                // multiple of 4
        int4  idx4 = *(const int4*)&g_idx[n];
        float4 zv  = *(const float4*)&z[i];
        float4 q;
        q.x = cb[(size_t)idx4.x * DIM + d];
        q.y = cb[(size_t)idx4.y * DIM + d];
        q.z = cb[(size_t)idx4.z * DIM + d];
        q.w = cb[(size_t)idx4.w * DIM + d];
        float4 o;
        float dx = __fsub_rn(q.x, zv.x); o.x = __fadd_rn(zv.x, dx);
        float dy = __fsub_rn(q.y, zv.y); o.y = __fadd_rn(zv.y, dy);
        float dz = __fsub_rn(q.z, zv.z); o.z = __fadd_rn(zv.z, dz);
        float dw = __fsub_rn(q.w, zv.w); o.w = __fadd_rn(zv.w, dw);
        *(float4*)&out[i] = o;
        local = __fmaf_rn(dx, dx, local);
        local = __fmaf_rn(dy, dy, local);
        local = __fmaf_rn(dz, dz, local);
        local = __fmaf_rn(dw, dw, local);
    }
    __shared__ float s[8];
    #pragma unroll
    for (int o = 16; o; o >>= 1) local += __shfl_down_sync(0xffffffffu, local, o);
    if ((threadIdx.x & 31) == 0) s[threadIdx.x >> 5] = local;
    __syncthreads();
    if (threadIdx.x < 8) {
        float t = s[threadIdx.x];
        #pragma unroll
        for (int o = 4; o; o >>= 1) t += __shfl_down_sync(0xffu, t, o);
        if (threadIdx.x == 0) {
            atomicAdd(&g_loss, (double)t);
            __threadfence();
            unsigned r = atomicAdd(&g_done, 1u);
            if (r == GL_BLOCKS - 1) {                 // last block: finalize
                double total = atomicAdd(&g_loss, 0.0);
                if (write_loss) out[LOSS_OFF] = (float)(1.25 * total / (double)ZQ_ELEMS);
                g_done = 0;                            // reset for next graph replay
            }
        }
    }
}

extern "C" void kernel_launch(void* const* d_in, const int* in_sizes, int n_in,
                              void* d_out, int out_size) {
    const float* z  = (const float*)d_in[0];
    const float* cb = (const float*)d_in[1];
    float* out = (float*)d_out;

    cudaFuncSetAttribute(gemm_hmma_k, cudaFuncAttributeMaxDynamicSharedMemorySize, HM_SMEM);

    int write_idx  = (out_size >= IDX_OFF + NPTS);
    int write_loss = (out_size >= LOSS_OFF + 1);

    norms_k<<<KCODE, 256>>>(cb);
    transpose_k<<<dim3(HW / 32, DIM / 32, BATCH), dim3(32, 8)>>>(z);
    rownorm_z_k<<<BATCH * 4, 256>>>(z);
    gemm_hmma_k<<<NPTS / 64, 128, HM_SMEM>>>();
    rescore_k<<<NPTS / 8, 256>>>(cb, out, write_idx);
    gather_loss_k<<<GL_BLOCKS, 256>>>(z, cb, out, write_loss);
}

// round 9
// speedup vs baseline: 1.3048x; 1.0528x over previous
#include <cuda_runtime.h>
#include <cuda_bf16.h>
#include <cstdint>

// Problem constants
#define BATCH 32
#define DIM   256
#define HW    1024
#define NPTS  32768
#define KCODE 1024
#define ZQ_ELEMS 8388608
#define IDX_OFF  ZQ_ELEMS
#define LOSS_OFF (ZQ_ELEMS + NPTS)

#define NSLOT 3           // top-3 per (thread,row) slot
#define NCROW 24          // 8 slots * 3 candidates per row
#define MARGIN 7e-4f

// Scratch (device globals)
__device__ float          g_zt [NPTS * DIM];     // z^T fp32 [N,D]
__device__ __nv_bfloat16  g_zth[NPTS * DIM];     // z^T bf16
__device__ __nv_bfloat16  g_cbh[KCODE * DIM];    // codebook bf16
__device__ int            g_idx[NPTS];
__device__ float          g_normE[KCODE];        // t2
__device__ float          g_t1[NPTS];            // t1 (sequential emulation)
__device__ float          g_candV[NPTS * NCROW];
__device__ int            g_candI[NPTS * NCROW];
__device__ double         g_loss;

// ================= generic PTX helpers =================
__device__ __forceinline__ uint32_t smem_u32(const void* p) {
    uint32_t a;
    asm("{ .reg .u64 t; cvta.to.shared.u64 t, %1; cvt.u32.u64 %0, t; }" : "=r"(a) : "l"(p));
    return a;
}
#define CP_ASYNC16(dst, src) \
    asm volatile("cp.async.cg.shared.global [%0], [%1], 16;" :: "r"(dst), "l"(src) : "memory")
#define CP_COMMIT() asm volatile("cp.async.commit_group;" ::: "memory")
#define CP_WAIT0()  asm volatile("cp.async.wait_group 0;" ::: "memory")
#define CP_WAIT1()  asm volatile("cp.async.wait_group 1;" ::: "memory")

#define LDSM4(r0, r1, r2, r3, addr) \
    asm volatile("ldmatrix.sync.aligned.m8n8.x4.shared.b16 {%0,%1,%2,%3}, [%4];" \
        : "=r"(r0), "=r"(r1), "=r"(r2), "=r"(r3) : "r"(addr))

#define MMA16816(C, A, b0, b1) \
    asm volatile("mma.sync.aligned.m16n8k16.row.col.f32.bf16.bf16.f32 " \
        "{%0,%1,%2,%3},{%4,%5,%6,%7},{%8,%9},{%0,%1,%2,%3};" \
        : "+f"((C)[0]), "+f"((C)[1]), "+f"((C)[2]), "+f"((C)[3]) \
        : "r"((A)[0]), "r"((A)[1]), "r"((A)[2]), "r"((A)[3]), "r"(b0), "r"(b1))

// swizzled smem offset for bf16 tile rows of 512B, 16B chunks
__device__ __forceinline__ uint32_t sw_off(int row, int c16) {
    return (uint32_t)(row * 512 + ((c16 ^ (row & 7)) << 4));
}

// ================= Kernel 1: codebook norms + bf16 cvt + loss reset =============
__global__ void norms_k(const float* __restrict__ cb) {
    int k = blockIdx.x;
    float x = cb[k * DIM + threadIdx.x];
    g_cbh[k * DIM + threadIdx.x] = __float2bfloat16(x);
    float v = __fmul_rn(x, x);
    __shared__ float s[8];
    #pragma unroll
    for (int o = 16; o; o >>= 1) v += __shfl_down_sync(0xffffffffu, v, o);
    if ((threadIdx.x & 31) == 0) s[threadIdx.x >> 5] = v;
    __syncthreads();
    if (threadIdx.x < 8) {
        float t = s[threadIdx.x];
        #pragma unroll
        for (int o = 4; o; o >>= 1) t += __shfl_down_sync(0xffu, t, o);
        if (threadIdx.x == 0) {
            g_normE[k] = t;
            if (blockIdx.x == 0) g_loss = 0.0;
        }
    }
}

// ================= Kernel 2: transpose z -> zt (f32 + bf16) =====================
__global__ void transpose_k(const float* __restrict__ z) {
    __shared__ float tile[32][33];
    int b  = blockIdx.z;
    int p0 = blockIdx.x * 32;
    int d0 = blockIdx.y * 32;
    const float* src = z + (size_t)b * DIM * HW;
    #pragma unroll
    for (int i = 0; i < 32; i += 8)
        tile[threadIdx.y + i][threadIdx.x] = src[(d0 + threadIdx.y + i) * HW + p0 + threadIdx.x];
    __syncthreads();
    #pragma unroll
    for (int i = 0; i < 32; i += 8) {
        float v = tile[threadIdx.x][threadIdx.y + i];
        int o = (b * HW + p0 + threadIdx.y + i) * DIM + d0 + threadIdx.x;
        g_zt[o]  = v;
        g_zth[o] = __float2bfloat16(v);
    }
}

// ================= Kernel 2b: t1 from original z layout (coalesced, seq order) ==
__global__ __launch_bounds__(256) void rownorm_z_k(const float* __restrict__ z) {
    int b = blockIdx.x >> 2;
    int p = ((blockIdx.x & 3) << 8) + threadIdx.x;
    const float* src = z + (size_t)b * DIM * HW + p;
    float acc = 0.0f;
    #pragma unroll 8
    for (int d = 0; d < 256; d++) {
        float x = src[(size_t)d * HW];
        acc = __fadd_rn(acc, __fmul_rn(x, x));   // strict d=0..255 sequential chain
    }
    g_t1[(b << 10) + p] = acc;
}

// ================= Kernel 3: HMMA bf16 GEMM (unchanged from R8) =================
// smem: A 32KB | B0 32KB | B1 32KB | NE 4KB = 100KB -> 2 CTAs/SM
#define AS_OFF 0
#define BS_OFF 32768
#define NE_OFF 98304
#define HM_SMEM 102400

__global__ __launch_bounds__(128, 2) void gemm_hmma_k() {
    extern __shared__ char smem[];
    const uint32_t sb = smem_u32(smem);
    const int tid  = threadIdx.x;
    const int lane = tid & 31;
    const int wid  = tid >> 5;
    const int wm   = wid & 1;
    const int wn   = wid >> 1;
    const int m0   = blockIdx.x * 64;

    #pragma unroll 4
    for (int i = tid; i < 2048; i += 128) {
        int row = i >> 5, c16 = i & 31;
        const __nv_bfloat16* src = &g_zth[(size_t)(m0 + row) * DIM + c16 * 8];
        CP_ASYNC16(sb + AS_OFF + sw_off(row, c16), (const void*)src);
    }
    #pragma unroll 4
    for (int i = tid; i < 2048; i += 128) {
        int row = i >> 5, c16 = i & 31;
        const __nv_bfloat16* src = &g_cbh[(size_t)row * DIM + c16 * 8];
        CP_ASYNC16(sb + BS_OFF + sw_off(row, c16), (const void*)src);
    }
    #pragma unroll
    for (int i = tid; i < 256; i += 128)
        CP_ASYNC16(sb + NE_OFF + i * 16, (const void*)&g_normE[i * 4]);
    CP_COMMIT();
    #pragma unroll 4
    for (int i = tid; i < 2048; i += 128) {
        int row = i >> 5, c16 = i & 31;
        const __nv_bfloat16* src = &g_cbh[(size_t)(64 + row) * DIM + c16 * 8];
        CP_ASYNC16(sb + BS_OFF + 32768 + sw_off(row, c16), (const void*)src);
    }
    CP_COMMIT();

    float tv[4][NSLOT];
    int   ts[4][NSLOT];
    #pragma unroll
    for (int s = 0; s < 4; s++)
        #pragma unroll
        for (int j = 0; j < NSLOT; j++) { tv[s][j] = 3.4e38f; ts[s][j] = 0; }

    const float2* nep = (const float2*)(smem + NE_OFF);

    const int arow = wm * 32 + (lane & 15);
    const int acol_sel = (lane >> 4);
    const int brow0 = wn * 32 + ((lane >> 4) & 1) * 8 + (lane & 7);
    const int bcol_sel = ((lane >> 3) & 1);

    for (int c = 0; c < 16; ++c) {
        if (c < 15) CP_WAIT1(); else CP_WAIT0();
        __syncthreads();

        const uint32_t Bbase = sb + BS_OFF + ((c & 1) << 15);
        float C[2][4][4];
        #pragma unroll
        for (int mt = 0; mt < 2; mt++)
            #pragma unroll
            for (int nt = 0; nt < 4; nt++)
                #pragma unroll
                for (int q = 0; q < 4; q++) C[mt][nt][q] = 0.0f;

        uint32_t a[2][2][4], b[2][2][4];
        {
            int c16 = acol_sel;
            LDSM4(a[0][0][0], a[0][0][1], a[0][0][2], a[0][0][3], sb + AS_OFF + sw_off(arow,      c16));
            LDSM4(a[0][1][0], a[0][1][1], a[0][1][2], a[0][1][3], sb + AS_OFF + sw_off(arow + 16, c16));
            int bc = bcol_sel;
            LDSM4(b[0][0][0], b[0][0][1], b[0][0][2], b[0][0][3], Bbase + sw_off(brow0,      bc));
            LDSM4(b[0][1][0], b[0][1][1], b[0][1][2], b[0][1][3], Bbase + sw_off(brow0 + 16, bc));
        }

        #pragma unroll
        for (int st = 0; st < 16; ++st) {
            const int cur = st & 1, nxt = cur ^ 1;
            if (st < 15) {
                int c16 = (st + 1) * 2 + acol_sel;
                LDSM4(a[nxt][0][0], a[nxt][0][1], a[nxt][0][2], a[nxt][0][3], sb + AS_OFF + sw_off(arow,      c16));
                LDSM4(a[nxt][1][0], a[nxt][1][1], a[nxt][1][2], a[nxt][1][3], sb + AS_OFF + sw_off(arow + 16, c16));
                int bc = (st + 1) * 2 + bcol_sel;
                LDSM4(b[nxt][0][0], b[nxt][0][1], b[nxt][0][2], b[nxt][0][3], Bbase + sw_off(brow0,      bc));
                LDSM4(b[nxt][1][0], b[nxt][1][1], b[nxt][1][2], b[nxt][1][3], Bbase + sw_off(brow0 + 16, bc));
            }
            #pragma unroll
            for (int mt = 0; mt < 2; mt++)
                #pragma unroll
                for (int nt = 0; nt < 4; nt++)
                    MMA16816(C[mt][nt], a[cur][mt], b[cur][nt >> 1][(nt & 1) * 2], b[cur][nt >> 1][(nt & 1) * 2 + 1]);
        }
        __syncthreads();

        if (c + 2 < 16) {
            #pragma unroll 4
            for (int i = tid; i < 2048; i += 128) {
                int row = i >> 5, c16 = i & 31;
                const __nv_bfloat16* src = &g_cbh[(size_t)((c + 2) * 64 + row) * DIM + c16 * 8];
                CP_ASYNC16(Bbase + sw_off(row, c16), (const void*)src);
            }
            CP_COMMIT();
        }

        #pragma unroll
        for (int mt = 0; mt < 2; mt++) {
            #pragma unroll
            for (int nt = 0; nt < 4; nt++) {
                int col = c * 64 + wn * 32 + nt * 8 + ((lane & 3) << 1);
                float2 ne = nep[col >> 1];
                float dv[4];
                dv[0] = __fmaf_rn(-2.0f, C[mt][nt][0], ne.x);
                dv[1] = __fmaf_rn(-2.0f, C[mt][nt][1], ne.y);
                dv[2] = __fmaf_rn(-2.0f, C[mt][nt][2], ne.x);
                dv[3] = __fmaf_rn(-2.0f, C[mt][nt][3], ne.y);
                #pragma unroll
                for (int q = 0; q < 4; q++) {
                    const int s = mt * 2 + (q >> 1);
                    const int idx = col + (q & 1);
                    const float v = dv[q];
                    if (v < tv[s][2]) {
                        if (v < tv[s][1]) {
                            tv[s][2] = tv[s][1]; ts[s][2] = ts[s][1];
                            if (v < tv[s][0]) {
                                tv[s][1] = tv[s][0]; ts[s][1] = ts[s][0];
                                tv[s][0] = v;        ts[s][0] = idx;
                            } else { tv[s][1] = v; ts[s][1] = idx; }
                        } else { tv[s][2] = v; ts[s][2] = idx; }
                    }
                }
            }
        }
    }

    #pragma unroll
    for (int mt = 0; mt < 2; mt++) {
        #pragma unroll
        for (int h = 0; h < 2; h++) {
            int row  = m0 + wm * 32 + mt * 16 + h * 8 + (lane >> 2);
            int slot = wn * 4 + (lane & 3);
            int s = mt * 2 + h;
            #pragma unroll
            for (int j = 0; j < NSLOT; j++) {
                g_candV[(size_t)row * NCROW + slot * NSLOT + j] = tv[s][j];
                g_candI[(size_t)row * NCROW + slot * NSLOT + j] = ts[s][j];
            }
        }
    }
}

// ================= Kernel 3b: rescore + idx output + LOSS accumulation ==========
// loss = sum_rows dist(row, chosen). Fast-path rows use t1 + approx bestV
// (abs err ~3e-5/row -> loss rel err ~1e-9); rescored rows use exact bestD.
__global__ __launch_bounds__(256) void rescore_k(const float* __restrict__ cb,
                                                 float* __restrict__ out, int write_idx) {
    const int wid  = threadIdx.x >> 5;
    const int lane = threadIdx.x & 31;
    const int row  = blockIdx.x * 8 + wid;
    const float* cv = &g_candV[(size_t)row * NCROW];
    const int*   ci = &g_candI[(size_t)row * NCROW];

    float v1 = (lane < NCROW) ? cv[lane] : 3.4e38f;
    int   i1 = (lane < NCROW) ? ci[lane] : 0;

    float vmin = v1;
    #pragma unroll
    for (int o = 16; o; o >>= 1) vmin = fminf(vmin, __shfl_xor_sync(0xffffffffu, vmin, o));
    const float thr = vmin + MARGIN;

    unsigned m1 = __ballot_sync(0xffffffffu, v1 <= thr);
    const float t1 = g_t1[row];

    int bestI;
    float lossRow;
    if (__popc(m1) == 1) {
        // unique candidate within margin: bf16 error << MARGIN => exact argmin.
        int wl = __ffs(m1) - 1;
        bestI = __shfl_sync(0xffffffffu, i1, wl);
        float vwin = __shfl_sync(0xffffffffu, v1, wl);
        lossRow = t1 + vwin;                      // approx dist; err ~3e-5 abs
    } else {
        const float4* zp = (const float4*)&g_zt[(size_t)row * DIM + lane * 8];
        const float4 za = zp[0], zb = zp[1];
        float bestD = 3.4e38f;
        bestI = 0x7fffffff;
        while (m1) {
            int l = __ffs(m1) - 1; m1 &= m1 - 1;
            int idx = __shfl_sync(0xffffffffu, i1, l);
            const float4* cp = (const float4*)&cb[(size_t)idx * DIM + lane * 8];
            float4 ca = cp[0], cb4 = cp[1];
            float p = 0.0f;
            p = __fmaf_rn(za.x, ca.x, p);  p = __fmaf_rn(za.y, ca.y, p);
            p = __fmaf_rn(za.z, ca.z, p);  p = __fmaf_rn(za.w, ca.w, p);
            p = __fmaf_rn(zb.x, cb4.x, p); p = __fmaf_rn(zb.y, cb4.y, p);
            p = __fmaf_rn(zb.z, cb4.z, p); p = __fmaf_rn(zb.w, cb4.w, p);
            #pragma unroll
            for (int o = 16; o; o >>= 1) p += __shfl_xor_sync(0xffffffffu, p, o);
            float dd = __fsub_rn(__fadd_rn(t1, __ldg(&g_normE[idx])), __fmul_rn(2.0f, p));
            if (dd < bestD || (dd == bestD && idx < bestI)) { bestD = dd; bestI = idx; }
        }
        bestI = __shfl_sync(0xffffffffu, bestI, 0);
        lossRow = __shfl_sync(0xffffffffu, bestD, 0);
    }

    __shared__ double sloss[8];
    if (lane == 0) {
        g_idx[row] = bestI;
        if (write_idx) out[IDX_OFF + row] = (float)bestI;
        sloss[wid] = (double)lossRow;
    }
    __syncthreads();
    if (threadIdx.x == 0) {
        double s = 0.0;
        #pragma unroll
        for (int w = 0; w < 8; w++) s += sloss[w];
        atomicAdd(&g_loss, s);
    }
}

// ================= Kernel 4: blocked gather z_q (coalesced cb reads) ============
// block = 64 consecutive positions; loads 64 codebook rows coalesced into smem,
// emits out[b][d][p] with 256B-coalesced writes; z read for exact straight-through.
__global__ __launch_bounds__(256) void gather_k(const float* __restrict__ z,
                                                const float* __restrict__ cb,
                                                float* __restrict__ out,
                                                int write_loss) {
    __shared__ float sq[64 * 257];     // [p][d], pad 257 kills read-phase conflicts
    __shared__ int   sidx[64];
    const int n0 = blockIdx.x * 64;
    const int b  = n0 >> 10, p0 = n0 & (HW - 1);

    if (threadIdx.x < 64) sidx[threadIdx.x] = g_idx[n0 + threadIdx.x];
    __syncthreads();
    // 64 rows x 64 float4 coalesced codebook loads
    for (int i = threadIdx.x; i < 4096; i += 256) {
        int r = i >> 6, c4 = i & 63;
        float4 v = ((const float4*)cb)[(size_t)sidx[r] * 64 + c4];
        float* dst = &sq[r * 257 + c4 * 4];
        dst[0] = v.x; dst[1] = v.y; dst[2] = v.z; dst[3] = v.w;
    }
    __syncthreads();

    const size_t base = (size_t)b * DIM * HW + p0;
    const int pp = threadIdx.x & 63;
    const int dh = threadIdx.x >> 6;       // 0..3
    #pragma unroll 4
    for (int j = 0; j < 64; j++) {
        int d = j * 4 + dh;
        float q  = sq[pp * 257 + d];
        float zv = z[base + (size_t)d * HW + pp];
        float diff = __fsub_rn(q, zv);
        out[base + (size_t)d * HW + pp] = __fadd_rn(zv, diff);   // == reference STE
    }
    if (blockIdx.x == 0 && threadIdx.x == 0 && write_loss)
        out[LOSS_OFF] = (float)(1.25 * g_loss / (double)ZQ_ELEMS);
}

extern "C" void kernel_launch(void* const* d_in, const int* in_sizes, int n_in,
                              void* d_out, int out_size) {
    const float* z  = (const float*)d_in[0];
    const float* cb = (const float*)d_in[1];
    float* out = (float*)d_out;

    cudaFuncSetAttribute(gemm_hmma_k, cudaFuncAttributeMaxDynamicSharedMemorySize, HM_SMEM);

    int write_idx  = (out_size >= IDX_OFF + NPTS);
    int write_loss = (out_size >= LOSS_OFF + 1);

    norms_k<<<KCODE, 256>>>(cb);
    transpose_k<<<dim3(HW / 32, DIM / 32, BATCH), dim3(32, 8)>>>(z);
    rownorm_z_k<<<BATCH * 4, 256>>>(z);
    gemm_hmma_k<<<NPTS / 64, 128, HM_SMEM>>>();
    rescore_k<<<NPTS / 8, 256>>>(cb, out, write_idx);
    gather_k<<<NPTS / 64, 256>>>(z, cb, out, write_loss);
}

// round 10
// speedup vs baseline: 1.3846x; 1.0612x over previous
#include <cuda_runtime.h>
#include <cuda_bf16.h>
#include <cstdint>

// Problem constants
#define BATCH 32
#define DIM   256
#define HW    1024
#define NPTS  32768
#define KCODE 1024
#define ZQ_ELEMS 8388608
#define IDX_OFF  ZQ_ELEMS
#define LOSS_OFF (ZQ_ELEMS + NPTS)

#define NSLOT 3           // top-3 per (thread,row) slot
#define NCROW 24          // 8 slots * 3 candidates per row
#define MARGIN 7e-4f

// Scratch (device globals)
__device__ float          g_zt [NPTS * DIM];     // z^T fp32 [N,D]
__device__ __nv_bfloat16  g_zth[NPTS * DIM];     // z^T bf16
__device__ __nv_bfloat16  g_cbh[KCODE * DIM];    // codebook bf16
__device__ int            g_idx[NPTS];
__device__ float          g_normE[KCODE];        // t2
__device__ float          g_t1[NPTS];            // t1 (sequential emulation)
__device__ float          g_candV[NPTS * NCROW];
__device__ int            g_candI[NPTS * NCROW];
__device__ double         g_loss;

// ================= generic PTX helpers =================
__device__ __forceinline__ uint32_t smem_u32(const void* p) {
    uint32_t a;
    asm("{ .reg .u64 t; cvta.to.shared.u64 t, %1; cvt.u32.u64 %0, t; }" : "=r"(a) : "l"(p));
    return a;
}
#define CP_ASYNC16(dst, src) \
    asm volatile("cp.async.cg.shared.global [%0], [%1], 16;" :: "r"(dst), "l"(src) : "memory")
#define CP_COMMIT() asm volatile("cp.async.commit_group;" ::: "memory")
#define CP_WAIT0()  asm volatile("cp.async.wait_group 0;" ::: "memory")
#define CP_WAIT1()  asm volatile("cp.async.wait_group 1;" ::: "memory")

#define LDSM4(r0, r1, r2, r3, addr) \
    asm volatile("ldmatrix.sync.aligned.m8n8.x4.shared.b16 {%0,%1,%2,%3}, [%4];" \
        : "=r"(r0), "=r"(r1), "=r"(r2), "=r"(r3) : "r"(addr))

#define MMA16816(C, A, b0, b1) \
    asm volatile("mma.sync.aligned.m16n8k16.row.col.f32.bf16.bf16.f32 " \
        "{%0,%1,%2,%3},{%4,%5,%6,%7},{%8,%9},{%0,%1,%2,%3};" \
        : "+f"((C)[0]), "+f"((C)[1]), "+f"((C)[2]), "+f"((C)[3]) \
        : "r"((A)[0]), "r"((A)[1]), "r"((A)[2]), "r"((A)[3]), "r"(b0), "r"(b1))

// swizzled smem offset for bf16 tile rows of 512B, 16B chunks
__device__ __forceinline__ uint32_t sw_off(int row, int c16) {
    return (uint32_t)(row * 512 + ((c16 ^ (row & 7)) << 4));
}

// ================= Kernel 1: codebook norms + bf16 cvt + loss reset =============
__global__ void norms_k(const float* __restrict__ cb) {
    int k = blockIdx.x;
    float x = cb[k * DIM + threadIdx.x];
    g_cbh[k * DIM + threadIdx.x] = __float2bfloat16(x);
    float v = __fmul_rn(x, x);
    __shared__ float s[8];
    #pragma unroll
    for (int o = 16; o; o >>= 1) v += __shfl_down_sync(0xffffffffu, v, o);
    if ((threadIdx.x & 31) == 0) s[threadIdx.x >> 5] = v;
    __syncthreads();
    if (threadIdx.x < 8) {
        float t = s[threadIdx.x];
        #pragma unroll
        for (int o = 4; o; o >>= 1) t += __shfl_down_sync(0xffu, t, o);
        if (threadIdx.x == 0) {
            g_normE[k] = t;
            if (blockIdx.x == 0) g_loss = 0.0;
        }
    }
}

// ================= Kernel 2: FUSED transpose + bf16 cvt + sequential t1 =========
// One block stages 32 positions x 256 d of z in smem (single z read), then
// emits zt (f32), zth (bf16) and the strict d=0..255 sequential t1 per row.
__global__ __launch_bounds__(256) void prep_k(const float* __restrict__ z) {
    __shared__ float sbuf[32][257];           // [p][d], 257 kills bank conflicts
    const int p0  = blockIdx.x * 32;
    const int b   = blockIdx.y;
    const int tid = threadIdx.x;
    const int tx  = tid & 31;                 // position lane
    const int ty  = tid >> 5;                 // 0..7

    const float* src = z + (size_t)b * DIM * HW + p0;
    for (int d = ty; d < DIM; d += 8)
        sbuf[tx][d] = src[(size_t)d * HW + tx];    // coalesced 128B per d
    __syncthreads();

    const int n0 = (b << 10) + p0;
    #pragma unroll 4
    for (int p = 0; p < 32; p++) {
        float v = sbuf[p][tid];
        size_t o = (size_t)(n0 + p) * DIM + tid;
        g_zt[o]  = v;                              // 1KB coalesced store
        g_zth[o] = __float2bfloat16(v);            // 512B coalesced store
    }

    if (tid < 32) {
        const float* row = &sbuf[tid][0];
        float acc = 0.0f;
        #pragma unroll 8
        for (int d = 0; d < DIM; d++)
            acc = __fadd_rn(acc, __fmul_rn(row[d], row[d]));   // strict seq chain
        g_t1[n0 + tid] = acc;
    }
}

// ================= Kernel 3: HMMA bf16 GEMM (frozen since R8) ===================
// smem: A 32KB | B0 32KB | B1 32KB | NE 4KB = 100KB -> 2 CTAs/SM
#define AS_OFF 0
#define BS_OFF 32768
#define NE_OFF 98304
#define HM_SMEM 102400

__global__ __launch_bounds__(128, 2) void gemm_hmma_k() {
    extern __shared__ char smem[];
    const uint32_t sb = smem_u32(smem);
    const int tid  = threadIdx.x;
    const int lane = tid & 31;
    const int wid  = tid >> 5;
    const int wm   = wid & 1;
    const int wn   = wid >> 1;
    const int m0   = blockIdx.x * 64;

    #pragma unroll 4
    for (int i = tid; i < 2048; i += 128) {
        int row = i >> 5, c16 = i & 31;
        const __nv_bfloat16* src = &g_zth[(size_t)(m0 + row) * DIM + c16 * 8];
        CP_ASYNC16(sb + AS_OFF + sw_off(row, c16), (const void*)src);
    }
    #pragma unroll 4
    for (int i = tid; i < 2048; i += 128) {
        int row = i >> 5, c16 = i & 31;
        const __nv_bfloat16* src = &g_cbh[(size_t)row * DIM + c16 * 8];
        CP_ASYNC16(sb + BS_OFF + sw_off(row, c16), (const void*)src);
    }
    #pragma unroll
    for (int i = tid; i < 256; i += 128)
        CP_ASYNC16(sb + NE_OFF + i * 16, (const void*)&g_normE[i * 4]);
    CP_COMMIT();
    #pragma unroll 4
    for (int i = tid; i < 2048; i += 128) {
        int row = i >> 5, c16 = i & 31;
        const __nv_bfloat16* src = &g_cbh[(size_t)(64 + row) * DIM + c16 * 8];
        CP_ASYNC16(sb + BS_OFF + 32768 + sw_off(row, c16), (const void*)src);
    }
    CP_COMMIT();

    float tv[4][NSLOT];
    int   ts[4][NSLOT];
    #pragma unroll
    for (int s = 0; s < 4; s++)
        #pragma unroll
        for (int j = 0; j < NSLOT; j++) { tv[s][j] = 3.4e38f; ts[s][j] = 0; }

    const float2* nep = (const float2*)(smem + NE_OFF);

    const int arow = wm * 32 + (lane & 15);
    const int acol_sel = (lane >> 4);
    const int brow0 = wn * 32 + ((lane >> 4) & 1) * 8 + (lane & 7);
    const int bcol_sel = ((lane >> 3) & 1);

    for (int c = 0; c < 16; ++c) {
        if (c < 15) CP_WAIT1(); else CP_WAIT0();
        __syncthreads();

        const uint32_t Bbase = sb + BS_OFF + ((c & 1) << 15);
        float C[2][4][4];
        #pragma unroll
        for (int mt = 0; mt < 2; mt++)
            #pragma unroll
            for (int nt = 0; nt < 4; nt++)
                #pragma unroll
                for (int q = 0; q < 4; q++) C[mt][nt][q] = 0.0f;

        uint32_t a[2][2][4], b[2][2][4];
        {
            int c16 = acol_sel;
            LDSM4(a[0][0][0], a[0][0][1], a[0][0][2], a[0][0][3], sb + AS_OFF + sw_off(arow,      c16));
            LDSM4(a[0][1][0], a[0][1][1], a[0][1][2], a[0][1][3], sb + AS_OFF + sw_off(arow + 16, c16));
            int bc = bcol_sel;
            LDSM4(b[0][0][0], b[0][0][1], b[0][0][2], b[0][0][3], Bbase + sw_off(brow0,      bc));
            LDSM4(b[0][1][0], b[0][1][1], b[0][1][2], b[0][1][3], Bbase + sw_off(brow0 + 16, bc));
        }

        #pragma unroll
        for (int st = 0; st < 16; ++st) {
            const int cur = st & 1, nxt = cur ^ 1;
            if (st < 15) {
                int c16 = (st + 1) * 2 + acol_sel;
                LDSM4(a[nxt][0][0], a[nxt][0][1], a[nxt][0][2], a[nxt][0][3], sb + AS_OFF + sw_off(arow,      c16));
                LDSM4(a[nxt][1][0], a[nxt][1][1], a[nxt][1][2], a[nxt][1][3], sb + AS_OFF + sw_off(arow + 16, c16));
                int bc = (st + 1) * 2 + bcol_sel;
                LDSM4(b[nxt][0][0], b[nxt][0][1], b[nxt][0][2], b[nxt][0][3], Bbase + sw_off(brow0,      bc));
                LDSM4(b[nxt][1][0], b[nxt][1][1], b[nxt][1][2], b[nxt][1][3], Bbase + sw_off(brow0 + 16, bc));
            }
            #pragma unroll
            for (int mt = 0; mt < 2; mt++)
                #pragma unroll
                for (int nt = 0; nt < 4; nt++)
                    MMA16816(C[mt][nt], a[cur][mt], b[cur][nt >> 1][(nt & 1) * 2], b[cur][nt >> 1][(nt & 1) * 2 + 1]);
        }
        __syncthreads();

        if (c + 2 < 16) {
            #pragma unroll 4
            for (int i = tid; i < 2048; i += 128) {
                int row = i >> 5, c16 = i & 31;
                const __nv_bfloat16* src = &g_cbh[(size_t)((c + 2) * 64 + row) * DIM + c16 * 8];
                CP_ASYNC16(Bbase + sw_off(row, c16), (const void*)src);
            }
            CP_COMMIT();
        }

        #pragma unroll
        for (int mt = 0; mt < 2; mt++) {
            #pragma unroll
            for (int nt = 0; nt < 4; nt++) {
                int col = c * 64 + wn * 32 + nt * 8 + ((lane & 3) << 1);
                float2 ne = nep[col >> 1];
                float dv[4];
                dv[0] = __fmaf_rn(-2.0f, C[mt][nt][0], ne.x);
                dv[1] = __fmaf_rn(-2.0f, C[mt][nt][1], ne.y);
                dv[2] = __fmaf_rn(-2.0f, C[mt][nt][2], ne.x);
                dv[3] = __fmaf_rn(-2.0f, C[mt][nt][3], ne.y);
                #pragma unroll
                for (int q = 0; q < 4; q++) {
                    const int s = mt * 2 + (q >> 1);
                    const int idx = col + (q & 1);
                    const float v = dv[q];
                    if (v < tv[s][2]) {
                        if (v < tv[s][1]) {
                            tv[s][2] = tv[s][1]; ts[s][2] = ts[s][1];
                            if (v < tv[s][0]) {
                                tv[s][1] = tv[s][0]; ts[s][1] = ts[s][0];
                                tv[s][0] = v;        ts[s][0] = idx;
                            } else { tv[s][1] = v; ts[s][1] = idx; }
                        } else { tv[s][2] = v; ts[s][2] = idx; }
                    }
                }
            }
        }
    }

    #pragma unroll
    for (int mt = 0; mt < 2; mt++) {
        #pragma unroll
        for (int h = 0; h < 2; h++) {
            int row  = m0 + wm * 32 + mt * 16 + h * 8 + (lane >> 2);
            int slot = wn * 4 + (lane & 3);
            int s = mt * 2 + h;
            #pragma unroll
            for (int j = 0; j < NSLOT; j++) {
                g_candV[(size_t)row * NCROW + slot * NSLOT + j] = tv[s][j];
                g_candI[(size_t)row * NCROW + slot * NSLOT + j] = ts[s][j];
            }
        }
    }
}

// ================= Kernel 4: rescore + idx output + loss accumulation ===========
__global__ __launch_bounds__(256) void rescore_k(const float* __restrict__ cb,
                                                 float* __restrict__ out, int write_idx) {
    const int wid  = threadIdx.x >> 5;
    const int lane = threadIdx.x & 31;
    const int row  = blockIdx.x * 8 + wid;
    const float* cv = &g_candV[(size_t)row * NCROW];
    const int*   ci = &g_candI[(size_t)row * NCROW];

    float v1 = (lane < NCROW) ? cv[lane] : 3.4e38f;
    int   i1 = (lane < NCROW) ? ci[lane] : 0;

    float vmin = v1;
    #pragma unroll
    for (int o = 16; o; o >>= 1) vmin = fminf(vmin, __shfl_xor_sync(0xffffffffu, vmin, o));
    const float thr = vmin + MARGIN;

    unsigned m1 = __ballot_sync(0xffffffffu, v1 <= thr);
    const float t1 = g_t1[row];

    int bestI;
    float lossRow;
    if (__popc(m1) == 1) {
        int wl = __ffs(m1) - 1;
        bestI = __shfl_sync(0xffffffffu, i1, wl);
        float vwin = __shfl_sync(0xffffffffu, v1, wl);
        lossRow = t1 + vwin;                      // approx dist; err ~3e-5 abs
    } else {
        const float4* zp = (const float4*)&g_zt[(size_t)row * DIM + lane * 8];
        const float4 za = zp[0], zb = zp[1];
        float bestD = 3.4e38f;
        bestI = 0x7fffffff;
        while (m1) {
            int l = __ffs(m1) - 1; m1 &= m1 - 1;
            int idx = __shfl_sync(0xffffffffu, i1, l);
            const float4* cp = (const float4*)&cb[(size_t)idx * DIM + lane * 8];
            float4 ca = cp[0], cb4 = cp[1];
            float p = 0.0f;
            p = __fmaf_rn(za.x, ca.x, p);  p = __fmaf_rn(za.y, ca.y, p);
            p = __fmaf_rn(za.z, ca.z, p);  p = __fmaf_rn(za.w, ca.w, p);
            p = __fmaf_rn(zb.x, cb4.x, p); p = __fmaf_rn(zb.y, cb4.y, p);
            p = __fmaf_rn(zb.z, cb4.z, p); p = __fmaf_rn(zb.w, cb4.w, p);
            #pragma unroll
            for (int o = 16; o; o >>= 1) p += __shfl_xor_sync(0xffffffffu, p, o);
            float dd = __fsub_rn(__fadd_rn(t1, __ldg(&g_normE[idx])), __fmul_rn(2.0f, p));
            if (dd < bestD || (dd == bestD && idx < bestI)) { bestD = dd; bestI = idx; }
        }
        bestI = __shfl_sync(0xffffffffu, bestI, 0);
        lossRow = __shfl_sync(0xffffffffu, bestD, 0);
    }

    __shared__ double sloss[8];
    if (lane == 0) {
        g_idx[row] = bestI;
        if (write_idx) out[IDX_OFF + row] = (float)bestI;
        sloss[wid] = (double)lossRow;
    }
    __syncthreads();
    if (threadIdx.x == 0) {
        double s = 0.0;
        #pragma unroll
        for (int w = 0; w < 8; w++) s += sloss[w];
        atomicAdd(&g_loss, s);
    }
}

// ================= Kernel 5: blocked gather z_q (coalesced cb reads) ============
__global__ __launch_bounds__(256) void gather_k(const float* __restrict__ z,
                                                const float* __restrict__ cb,
                                                float* __restrict__ out,
                                                int write_loss) {
    __shared__ float sq[64 * 257];     // [p][d], pad 257 kills read-phase conflicts
    __shared__ int   sidx[64];
    const int n0 = blockIdx.x * 64;
    const int b  = n0 >> 10, p0 = n0 & (HW - 1);

    if (threadIdx.x < 64) sidx[threadIdx.x] = g_idx[n0 + threadIdx.x];
    __syncthreads();
    for (int i = threadIdx.x; i < 4096; i += 256) {
        int r = i >> 6, c4 = i & 63;
        float4 v = ((const float4*)cb)[(size_t)sidx[r] * 64 + c4];
        float* dst = &sq[r * 257 + c4 * 4];
        dst[0] = v.x; dst[1] = v.y; dst[2] = v.z; dst[3] = v.w;
    }
    __syncthreads();

    const size_t base = (size_t)b * DIM * HW + p0;
    const int pp = threadIdx.x & 63;
    const int dh = threadIdx.x >> 6;       // 0..3
    #pragma unroll 4
    for (int j = 0; j < 64; j++) {
        int d = j * 4 + dh;
        float q  = sq[pp * 257 + d];
        float zv = z[base + (size_t)d * HW + pp];
        float diff = __fsub_rn(q, zv);
        out[base + (size_t)d * HW + pp] = __fadd_rn(zv, diff);   // == reference STE
    }
    if (blockIdx.x == 0 && threadIdx.x == 0 && write_loss)
        out[LOSS_OFF] = (float)(1.25 * g_loss / (double)ZQ_ELEMS);
}

extern "C" void kernel_launch(void* const* d_in, const int* in_sizes, int n_in,
                              void* d_out, int out_size) {
    const float* z  = (const float*)d_in[0];
    const float* cb = (const float*)d_in[1];
    float* out = (float*)d_out;

    cudaFuncSetAttribute(gemm_hmma_k, cudaFuncAttributeMaxDynamicSharedMemorySize, HM_SMEM);

    int write_idx  = (out_size >= IDX_OFF + NPTS);
    int write_loss = (out_size >= LOSS_OFF + 1);

    norms_k<<<KCODE, 256>>>(cb);
    prep_k<<<dim3(HW / 32, BATCH), 256>>>(z);
    gemm_hmma_k<<<NPTS / 64, 128, HM_SMEM>>>();
    rescore_k<<<NPTS / 8, 256>>>(cb, out, write_idx);
    gather_k<<<NPTS / 64, 256>>>(z, cb, out, write_loss);
}